// round 8
// baseline (speedup 1.0000x reference)
#include <cuda_runtime.h>
#include <cuda_bf16.h>
#include <math.h>
#include <stdint.h>

#define FEAT   128
#define NN     512
#define BATCH  4
#define NSAMP  5
#define E_CNT  97920
#define BASE0  32896
#define TILE_M 128
#define NTILE  (E_CNT / TILE_M)     // 765
#define DELTA  0.125f
#define MAXC   128
#define XS     68                   // word stride of bf16 tiles (conflict-free)
#define SMEM_X_BYTES (128 * XS * 4) // 34816
#define SMEM_MAIN (2 * SMEM_X_BYTES)

// ---------------------------------------------------------------------------
// Scratch (static device globals: no allocation allowed)
// ---------------------------------------------------------------------------
__device__ float    g_A[BATCH * NN * FEAT];
__device__ float    g_Bm[BATCH * NN * FEAT];
__device__ float    g_scores[BATCH * NSAMP * E_CNT];   // 7.8 MB
__device__ unsigned g_bestu[BATCH * NSAMP];            // flipped-float approx max
__device__ int      g_winner[BATCH * NSAMP];

// ---------------------------------------------------------------------------
// helpers
// ---------------------------------------------------------------------------
__device__ __forceinline__ unsigned flipf(float f) {
    unsigned u = __float_as_uint(f);
    return (u & 0x80000000u) ? ~u : (u | 0x80000000u);
}
__device__ __forceinline__ float unflipf(unsigned u) {
    return __uint_as_float((u & 0x80000000u) ? (u & 0x7FFFFFFFu) : ~u);
}
__device__ __forceinline__ unsigned rotl32(unsigned v, int s) {
    return (v << s) | (v >> (32 - s));
}
// JAX Threefry-2x32, key (0,42), partitionable: bits[j] = v0^v1 of tf((0,42),(0,j))
__device__ __forceinline__ unsigned threefry_bits(unsigned j) {
    const unsigned ks0 = 0u, ks1 = 42u, ks2 = 0x1BD11BDAu ^ 42u;
    unsigned x0 = ks0, x1 = j + ks1;
#define RND(r) { x0 += x1; x1 = rotl32(x1, (r)); x1 ^= x0; }
    RND(13) RND(15) RND(26) RND(6)
    x0 += ks1; x1 += ks2 + 1u;
    RND(17) RND(29) RND(16) RND(24)
    x0 += ks2; x1 += ks0 + 2u;
    RND(13) RND(15) RND(26) RND(6)
    x0 += ks0; x1 += ks1 + 3u;
    RND(17) RND(29) RND(16) RND(24)
    x0 += ks1; x1 += ks2 + 4u;
    RND(13) RND(15) RND(26) RND(6)
    x0 += ks2; x1 += ks0 + 5u;
#undef RND
    return x0 ^ x1;
}
__device__ __forceinline__ float gumbel_from_bits(unsigned bits) {
    unsigned m = bits >> 9;
    float u;
    if (m == 0u) u = 1.17549435e-38f;
    else         u = __uint_as_float(0x3F800000u | m) - 1.0f;
    return -logf(-logf(u));
}
__device__ __forceinline__ void decode_edge(int e, int &r, int &c) {
    int t = e + BASE0;
    int rr = (int)((1.0f + sqrtf(8.0f * (float)t + 1.0f)) * 0.5f);
    while (rr * (rr - 1) / 2 > t) --rr;
    while ((rr + 1) * rr / 2 <= t) ++rr;
    r = rr;
    c = t - rr * (rr - 1) / 2;
}
__device__ __forceinline__ float warp_sum(float v) {
    v += __shfl_xor_sync(0xffffffffu, v, 16);
    v += __shfl_xor_sync(0xffffffffu, v, 8);
    v += __shfl_xor_sync(0xffffffffu, v, 4);
    v += __shfl_xor_sync(0xffffffffu, v, 2);
    v += __shfl_xor_sync(0xffffffffu, v, 1);
    return v;
}
// bf16 HMMA m16n8k16, row.col, fp32 accum
__device__ __forceinline__ void mma16816(float4 &d, const uint32_t a[4],
                                         uint32_t b0, uint32_t b1) {
    asm volatile(
        "mma.sync.aligned.m16n8k16.row.col.f32.bf16.bf16.f32 "
        "{%0,%1,%2,%3}, {%4,%5,%6,%7}, {%8,%9}, {%0,%1,%2,%3};"
        : "+f"(d.x), "+f"(d.y), "+f"(d.z), "+f"(d.w)
        : "r"(a[0]), "r"(a[1]), "r"(a[2]), "r"(a[3]), "r"(b0), "r"(b1));
}

// ---------------------------------------------------------------------------
// Kernel 0: zero output + reset approx maxima
// ---------------------------------------------------------------------------
__global__ void init_kernel(float4 *out) {
    int i = blockIdx.x * blockDim.x + threadIdx.x;
    if (i < (BATCH * NN * NN) / 4) out[i] = make_float4(0.f, 0.f, 0.f, 0.f);
    if (blockIdx.x == 0 && threadIdx.x < BATCH * NSAMP) g_bestu[threadIdx.x] = 0u;
}

// ---------------------------------------------------------------------------
// Kernel 1: per-node layer-1 partials (8 nodes per block)
// ---------------------------------------------------------------------------
__global__ void precompute_kernel(const float *__restrict__ nodes,
                                  const float *__restrict__ W1) {
    int f  = threadIdx.x;
    int nb = blockIdx.x * 8;
    __shared__ float sn[8][FEAT];
#pragma unroll
    for (int k = 0; k < 8; ++k) sn[k][f] = nodes[(nb + k) * FEAT + f];
    __syncthreads();
    float a[8], bb[8];
#pragma unroll
    for (int k = 0; k < 8; ++k) { a[k] = 0.f; bb[k] = 0.f; }
    for (int i = 0; i < FEAT; ++i) {
        float wt = W1[i * FEAT + f];
        float wb = W1[(i + FEAT) * FEAT + f];
#pragma unroll
        for (int k = 0; k < 8; ++k) {
            a[k]  += sn[k][i] * wt;
            bb[k] += sn[k][i] * wb;
        }
    }
#pragma unroll
    for (int k = 0; k < 8; ++k) {
        g_A[(nb + k) * FEAT + f]  = a[k];
        g_Bm[(nb + k) * FEAT + f] = bb[k];
    }
}

// ---------------------------------------------------------------------------
// Kernel 2: bf16 HMMA approx pass. 128 edges per block, 4 warps.
// ---------------------------------------------------------------------------
extern __shared__ uint32_t smem_w[];

__global__ void __launch_bounds__(128)
main_mma(const float *__restrict__ b1,  const float *__restrict__ g1,
         const float *__restrict__ be1, const float *__restrict__ W2,
         const float *__restrict__ b2,  const float *__restrict__ g2,
         const float *__restrict__ be2, const float *__restrict__ W3,
         const float *__restrict__ b3) {
    const int tid = threadIdx.x, lane = tid & 31, warp = tid >> 5;
    const int gr = lane >> 2, tg = lane & 3;
    const int b = blockIdx.y;
    const int ebase = blockIdx.x * TILE_M;

    uint32_t *Xw = smem_w;                       // bf16 X tile [128][XS words]
    uint32_t *Ww = smem_w + 128 * XS;            // bf16 W2^T   [128][XS words]
    __shared__ float2   sPar[FEAT];              // (b2[c], g2[c]*W3[c])
    __shared__ float    sSP, sSQ;
    __shared__ unsigned sBest[NSAMP];

    // stage W2^T as bf16: Ww row n holds W2[:, n] over k
    {
        __nv_bfloat16 *W16 = (__nv_bfloat16 *)Ww;
        for (int idx = tid; idx < FEAT * FEAT; idx += 128) {
            int k = idx >> 7, n = idx & 127;
            W16[n * (2 * XS) + k] = __float2bfloat16(W2[idx]);
        }
    }
    // params
    sPar[tid] = make_float2(__ldg(b2 + tid), __ldg(g2 + tid) * __ldg(W3 + tid));
    if (tid < NSAMP) sBest[tid] = 0u;
    if (warp == 0) {
        float p = 0.f, q = 0.f;
#pragma unroll
        for (int c = lane; c < FEAT; c += 32) {
            float w3 = __ldg(W3 + c);
            p += __ldg(g2 + c) * w3;
            q += __ldg(be2 + c) * w3;
        }
        p = warp_sum(p);
        q = warp_sum(q);
        if (lane == 0) { sSP = p; sSQ = q; }
    }

    // Phase A: layer-1 + LN -> bf16 X rows (warp handles 32 edges)
    float c_b1[4], c_g1[4], c_be1[4];
#pragma unroll
    for (int k = 0; k < 4; ++k) {
        int f = lane * 4 + k;
        c_b1[k] = __ldg(b1 + f); c_g1[k] = __ldg(g1 + f); c_be1[k] = __ldg(be1 + f);
    }
    const float *Ab = g_A  + b * NN * FEAT;
    const float *Bb = g_Bm + b * NN * FEAT;
    const int m0 = warp * 32;
#pragma unroll 4
    for (int t = 0; t < 32; ++t) {
        int m = m0 + t;
        int r, c;
        decode_edge(ebase + m, r, c);
        float4 av = *(const float4 *)(Ab + r * FEAT + lane * 4);
        float4 bv = *(const float4 *)(Bb + c * FEAT + lane * 4);
        float h0 = fmaxf(av.x + bv.x + c_b1[0], 0.f);
        float h1 = fmaxf(av.y + bv.y + c_b1[1], 0.f);
        float h2 = fmaxf(av.z + bv.z + c_b1[2], 0.f);
        float h3 = fmaxf(av.w + bv.w + c_b1[3], 0.f);
        float mu = warp_sum(h0 + h1 + h2 + h3) * (1.f / 128.f);
        float d0 = h0 - mu, d1 = h1 - mu, d2 = h2 - mu, d3 = h3 - mu;
        float var = warp_sum(d0 * d0 + d1 * d1 + d2 * d2 + d3 * d3) * (1.f / 128.f);
        float inv = rsqrtf(var + 1e-5f);
        float x0 = d0 * inv * c_g1[0] + c_be1[0];
        float x1 = d1 * inv * c_g1[1] + c_be1[1];
        float x2 = d2 * inv * c_g1[2] + c_be1[2];
        float x3 = d3 * inv * c_g1[3] + c_be1[3];
        __nv_bfloat162 p0 = __floats2bfloat162_rn(x0, x1);
        __nv_bfloat162 p1 = __floats2bfloat162_rn(x2, x3);
        uint2 pk;
        pk.x = *(uint32_t *)&p0;
        pk.y = *(uint32_t *)&p1;
        *(uint2 *)(Xw + m * XS + lane * 2) = pk;
    }
    __syncthreads();

    // MMA: D[128,128] = X @ W2 ; warp owns 2 m16-tiles, 16 n8-tiles, 8 k16-steps
    float4 d[2][16];
#pragma unroll
    for (int mt = 0; mt < 2; ++mt)
#pragma unroll
        for (int nt = 0; nt < 16; ++nt) d[mt][nt] = make_float4(0.f, 0.f, 0.f, 0.f);

    for (int kt = 0; kt < 8; ++kt) {
        const int kw = kt * 8 + tg;
        uint32_t a[2][4];
#pragma unroll
        for (int mt = 0; mt < 2; ++mt) {
            int rowb = m0 + mt * 16 + gr;
            a[mt][0] = Xw[rowb * XS + kw];
            a[mt][1] = Xw[(rowb + 8) * XS + kw];
            a[mt][2] = Xw[rowb * XS + kw + 4];
            a[mt][3] = Xw[(rowb + 8) * XS + kw + 4];
        }
#pragma unroll
        for (int nt = 0; nt < 16; ++nt) {
            uint32_t b0 = Ww[(nt * 8 + gr) * XS + kw];
            uint32_t b1v = Ww[(nt * 8 + gr) * XS + kw + 4];
            mma16816(d[0][nt], a[0], b0, b1v);
            mma16816(d[1][nt], a[1], b0, b1v);
        }
    }

    // Epilogue in fragments: single pass -> S1, S2, SP per row-slot
    const float b3v = __ldg(b3);
    unsigned bestA = 0u, bestB = 0u;
#pragma unroll
    for (int rs = 0; rs < 4; ++rs) {
        const int mt = rs >> 1, hi = rs & 1;
        float S1 = 0.f, S2 = 0.f, SP = 0.f;
#pragma unroll
        for (int nt = 0; nt < 16; ++nt) {
            float4 par = *(const float4 *)&sPar[nt * 8 + tg * 2];
            float v0 = hi ? d[mt][nt].z : d[mt][nt].x;
            float v1 = hi ? d[mt][nt].w : d[mt][nt].y;
            float h0 = fmaxf(v0 + par.x, 0.f);
            float h1 = fmaxf(v1 + par.z, 0.f);
            S1 += h0 + h1;
            S2 += h0 * h0 + h1 * h1;
            SP += h0 * par.y + h1 * par.w;
        }
        S1 += __shfl_xor_sync(0xffffffffu, S1, 1);
        S1 += __shfl_xor_sync(0xffffffffu, S1, 2);
        S2 += __shfl_xor_sync(0xffffffffu, S2, 1);
        S2 += __shfl_xor_sync(0xffffffffu, S2, 2);
        SP += __shfl_xor_sync(0xffffffffu, SP, 1);
        SP += __shfl_xor_sync(0xffffffffu, SP, 2);
        float mu  = S1 * (1.f / 128.f);
        float var = fmaxf(S2 * (1.f / 128.f) - mu * mu, 0.f);
        float inv = rsqrtf(var + 1e-5f);
        float logit = inv * SP - mu * inv * sSP + sSQ + b3v;

        int e = ebase + m0 + mt * 16 + hi * 8 + gr;
        unsigned j = (unsigned)((b * NSAMP + tg) * E_CNT + e);
        float sc = logit + gumbel_from_bits(threefry_bits(j));
        g_scores[j] = sc;
        bestA = max(bestA, flipf(sc));
        if (tg == 0) {
            unsigned j4 = (unsigned)((b * NSAMP + 4) * E_CNT + e);
            float sc4 = logit + gumbel_from_bits(threefry_bits(j4));
            g_scores[j4] = sc4;
            bestB = max(bestB, flipf(sc4));
        }
    }
    bestA = max(bestA, __shfl_xor_sync(0xffffffffu, bestA, 4));
    bestA = max(bestA, __shfl_xor_sync(0xffffffffu, bestA, 8));
    bestA = max(bestA, __shfl_xor_sync(0xffffffffu, bestA, 16));
    bestB = max(bestB, __shfl_xor_sync(0xffffffffu, bestB, 4));
    bestB = max(bestB, __shfl_xor_sync(0xffffffffu, bestB, 8));
    bestB = max(bestB, __shfl_xor_sync(0xffffffffu, bestB, 16));
    if (lane < 4) atomicMax(&sBest[lane], bestA);
    if (lane == 0) atomicMax(&sBest[4], bestB);
    __syncthreads();
    if (tid < NSAMP) atomicMax(&g_bestu[b * NSAMP + tid], sBest[tid]);
}

// ---------------------------------------------------------------------------
// Exact fp32 score for one edge, warp-collective (R2/R3-validated op order)
// ---------------------------------------------------------------------------
__device__ float exact_score(int e, int b, int s,
                             const float *W2, const float *b1, const float *g1,
                             const float *be1, const float *b2, const float *g2,
                             const float *be2, const float *W3, const float *b3,
                             int lane) {
    int r, c;
    decode_edge(e, r, c);
    const float *Ab = g_A  + b * NN * FEAT;
    const float *Bb = g_Bm + b * NN * FEAT;
    float4 av = *(const float4 *)(Ab + r * FEAT + lane * 4);
    float4 bv = *(const float4 *)(Bb + c * FEAT + lane * 4);
    int f = lane * 4;
    float h0 = fmaxf(av.x + bv.x + __ldg(b1 + f + 0), 0.f);
    float h1 = fmaxf(av.y + bv.y + __ldg(b1 + f + 1), 0.f);
    float h2 = fmaxf(av.z + bv.z + __ldg(b1 + f + 2), 0.f);
    float h3 = fmaxf(av.w + bv.w + __ldg(b1 + f + 3), 0.f);
    float mu = warp_sum(h0 + h1 + h2 + h3) * (1.f / 128.f);
    float d0 = h0 - mu, d1 = h1 - mu, d2 = h2 - mu, d3 = h3 - mu;
    float var = warp_sum(d0 * d0 + d1 * d1 + d2 * d2 + d3 * d3) * (1.f / 128.f);
    float inv = rsqrtf(var + 1e-5f);
    float x0 = d0 * inv * __ldg(g1 + f + 0) + __ldg(be1 + f + 0);
    float x1 = d1 * inv * __ldg(g1 + f + 1) + __ldg(be1 + f + 1);
    float x2 = d2 * inv * __ldg(g1 + f + 2) + __ldg(be1 + f + 2);
    float x3 = d3 * inv * __ldg(g1 + f + 3) + __ldg(be1 + f + 3);

    float a0 = 0.f, a1 = 0.f, a2 = 0.f, a3 = 0.f;
    for (int src = 0; src < 32; ++src) {
        float v0 = __shfl_sync(0xffffffffu, x0, src);
        float v1 = __shfl_sync(0xffffffffu, x1, src);
        float v2 = __shfl_sync(0xffffffffu, x2, src);
        float v3 = __shfl_sync(0xffffffffu, x3, src);
        float4 w;
        w = *(const float4 *)(W2 + (src * 4 + 0) * FEAT + f);
        a0 += v0 * w.x; a1 += v0 * w.y; a2 += v0 * w.z; a3 += v0 * w.w;
        w = *(const float4 *)(W2 + (src * 4 + 1) * FEAT + f);
        a0 += v1 * w.x; a1 += v1 * w.y; a2 += v1 * w.z; a3 += v1 * w.w;
        w = *(const float4 *)(W2 + (src * 4 + 2) * FEAT + f);
        a0 += v2 * w.x; a1 += v2 * w.y; a2 += v2 * w.z; a3 += v2 * w.w;
        w = *(const float4 *)(W2 + (src * 4 + 3) * FEAT + f);
        a0 += v3 * w.x; a1 += v3 * w.y; a2 += v3 * w.z; a3 += v3 * w.w;
    }
    h0 = fmaxf(a0 + __ldg(b2 + f + 0), 0.f);
    h1 = fmaxf(a1 + __ldg(b2 + f + 1), 0.f);
    h2 = fmaxf(a2 + __ldg(b2 + f + 2), 0.f);
    h3 = fmaxf(a3 + __ldg(b2 + f + 3), 0.f);
    mu = warp_sum(h0 + h1 + h2 + h3) * (1.f / 128.f);
    d0 = h0 - mu; d1 = h1 - mu; d2 = h2 - mu; d3 = h3 - mu;
    var = warp_sum(d0 * d0 + d1 * d1 + d2 * d2 + d3 * d3) * (1.f / 128.f);
    inv = rsqrtf(var + 1e-5f);
    float y0 = d0 * inv * __ldg(g2 + f + 0) + __ldg(be2 + f + 0);
    float y1 = d1 * inv * __ldg(g2 + f + 1) + __ldg(be2 + f + 1);
    float y2 = d2 * inv * __ldg(g2 + f + 2) + __ldg(be2 + f + 2);
    float y3 = d3 * inv * __ldg(g2 + f + 3) + __ldg(be2 + f + 3);
    float logit = warp_sum(y0 * __ldg(W3 + f + 0) + y1 * __ldg(W3 + f + 1) +
                           y2 * __ldg(W3 + f + 2) + y3 * __ldg(W3 + f + 3)) + __ldg(b3);
    unsigned j = (unsigned)((b * NSAMP + s) * E_CNT + e);
    return logit + gumbel_from_bits(threefry_bits(j));
}

// ---------------------------------------------------------------------------
// Kernel 3: per-(b,s) candidate collection + exact refinement + argmax
// ---------------------------------------------------------------------------
__global__ void __launch_bounds__(256)
refine_kernel(const float *__restrict__ W2, const float *__restrict__ b1,
              const float *__restrict__ g1, const float *__restrict__ be1,
              const float *__restrict__ b2, const float *__restrict__ g2,
              const float *__restrict__ be2, const float *__restrict__ W3,
              const float *__restrict__ b3) {
    const int bs = blockIdx.x;
    const int b = bs / NSAMP, s = bs % NSAMP;
    __shared__ int   s_cnt;
    __shared__ int   s_cand[MAXC];
    __shared__ float s_score[MAXC];
    if (threadIdx.x == 0) s_cnt = 0;
    __syncthreads();

    const float bestA = unflipf(g_bestu[bs]);
    const float thr = bestA - DELTA;
    const float *sc = g_scores + bs * E_CNT;
    for (int e = threadIdx.x; e < E_CNT; e += blockDim.x) {
        if (sc[e] >= thr) {
            int i = atomicAdd(&s_cnt, 1);
            if (i < MAXC) s_cand[i] = e;
        }
    }
    __syncthreads();
    int n = min(s_cnt, MAXC);

    const int warp = threadIdx.x >> 5, lane = threadIdx.x & 31;
    for (int i = warp; i < n; i += 8) {
        float v = exact_score(s_cand[i], b, s, W2, b1, g1, be1, b2, g2, be2, W3, b3, lane);
        if (lane == 0) s_score[i] = v;
    }
    __syncthreads();
    if (threadIdx.x == 0) {
        float best = -__int_as_float(0x7f800000);
        int beste = 0x7FFFFFFF;
        for (int i = 0; i < n; ++i) {
            if (s_score[i] > best || (s_score[i] == best && s_cand[i] < beste)) {
                best = s_score[i];
                beste = s_cand[i];
            }
        }
        g_winner[bs] = beste;
    }
}

// ---------------------------------------------------------------------------
// Kernel 4: scatter winners
// ---------------------------------------------------------------------------
__global__ void finalize_kernel(float *out) {
    int t = threadIdx.x;
    if (t >= BATCH * NSAMP) return;
    int e = g_winner[t];
    int b = t / NSAMP;
    int r, c;
    decode_edge(e, r, c);
    out[b * NN * NN + r * NN + c] = 1.0f;
}

// ---------------------------------------------------------------------------
extern "C" void kernel_launch(void *const *d_in, const int *in_sizes, int n_in,
                              void *d_out, int out_size) {
    const float *nodes = (const float *)d_in[0];
    const float *W1    = (const float *)d_in[1];
    const float *b1    = (const float *)d_in[2];
    const float *g1    = (const float *)d_in[3];
    const float *be1   = (const float *)d_in[4];
    const float *W2    = (const float *)d_in[5];
    const float *b2    = (const float *)d_in[6];
    const float *g2    = (const float *)d_in[7];
    const float *be2   = (const float *)d_in[8];
    const float *W3    = (const float *)d_in[9];
    const float *b3    = (const float *)d_in[10];

    cudaFuncSetAttribute(main_mma, cudaFuncAttributeMaxDynamicSharedMemorySize, SMEM_MAIN);

    init_kernel<<<1024, 256>>>((float4 *)d_out);
    precompute_kernel<<<BATCH * NN / 8, FEAT>>>(nodes, W1);
    main_mma<<<dim3(NTILE, BATCH), 128, SMEM_MAIN>>>(
        b1, g1, be1, W2, b2, g2, be2, W3, b3);
    refine_kernel<<<BATCH * NSAMP, 256>>>(W2, b1, g1, be1, b2, g2, be2, W3, b3);
    finalize_kernel<<<1, 32>>>((float *)d_out);
}

// round 9
// speedup vs baseline: 1.0006x; 1.0006x over previous
#include <cuda_runtime.h>
#include <cuda_bf16.h>
#include <math.h>
#include <stdint.h>

#define FEAT   128
#define NN     512
#define BATCH  4
#define NSAMP  5
#define E_CNT  97920
#define BASE0  32896
#define TILE_M 128
#define NTILE  (E_CNT / TILE_M)     // 765
#define DELTA  0.125f
#define MAXC   128
#define XS     68                   // word stride of bf16 tiles (conflict-free)
#define SMEM_X_BYTES (128 * XS * 4) // 34816
#define SMEM_MAIN (2 * SMEM_X_BYTES)

// ---------------------------------------------------------------------------
// Scratch (static device globals: no allocation allowed)
// ---------------------------------------------------------------------------
__device__ float    g_A[BATCH * NN * FEAT];
__device__ float    g_Bm[BATCH * NN * FEAT];
__device__ float    g_scores[BATCH * NSAMP * E_CNT];   // 7.8 MB
__device__ unsigned g_bestu[BATCH * NSAMP];            // flipped-float approx max
__device__ int      g_winner[BATCH * NSAMP];

// ---------------------------------------------------------------------------
// helpers
// ---------------------------------------------------------------------------
__device__ __forceinline__ unsigned flipf(float f) {
    unsigned u = __float_as_uint(f);
    return (u & 0x80000000u) ? ~u : (u | 0x80000000u);
}
__device__ __forceinline__ float unflipf(unsigned u) {
    return __uint_as_float((u & 0x80000000u) ? (u & 0x7FFFFFFFu) : ~u);
}
__device__ __forceinline__ unsigned rotl32(unsigned v, int s) {
    return (v << s) | (v >> (32 - s));
}
// JAX Threefry-2x32, key (0,42), partitionable: bits[j] = v0^v1 of tf((0,42),(0,j))
__device__ __forceinline__ unsigned threefry_bits(unsigned j) {
    const unsigned ks0 = 0u, ks1 = 42u, ks2 = 0x1BD11BDAu ^ 42u;
    unsigned x0 = ks0, x1 = j + ks1;
#define RND(r) { x0 += x1; x1 = rotl32(x1, (r)); x1 ^= x0; }
    RND(13) RND(15) RND(26) RND(6)
    x0 += ks1; x1 += ks2 + 1u;
    RND(17) RND(29) RND(16) RND(24)
    x0 += ks2; x1 += ks0 + 2u;
    RND(13) RND(15) RND(26) RND(6)
    x0 += ks0; x1 += ks1 + 3u;
    RND(17) RND(29) RND(16) RND(24)
    x0 += ks1; x1 += ks2 + 4u;
    RND(13) RND(15) RND(26) RND(6)
    x0 += ks2; x1 += ks0 + 5u;
#undef RND
    return x0 ^ x1;
}
__device__ __forceinline__ float gumbel_from_bits(unsigned bits) {
    unsigned m = bits >> 9;
    float u;
    if (m == 0u) u = 1.17549435e-38f;
    else         u = __uint_as_float(0x3F800000u | m) - 1.0f;
    return -logf(-logf(u));
}
__device__ __forceinline__ void decode_edge(int e, int &r, int &c) {
    int t = e + BASE0;
    int rr = (int)((1.0f + sqrtf(8.0f * (float)t + 1.0f)) * 0.5f);
    while (rr * (rr - 1) / 2 > t) --rr;
    while ((rr + 1) * rr / 2 <= t) ++rr;
    r = rr;
    c = t - rr * (rr - 1) / 2;
}
__device__ __forceinline__ float warp_sum(float v) {
    v += __shfl_xor_sync(0xffffffffu, v, 16);
    v += __shfl_xor_sync(0xffffffffu, v, 8);
    v += __shfl_xor_sync(0xffffffffu, v, 4);
    v += __shfl_xor_sync(0xffffffffu, v, 2);
    v += __shfl_xor_sync(0xffffffffu, v, 1);
    return v;
}
// bf16 HMMA m16n8k16, row.col, fp32 accum
__device__ __forceinline__ void mma16816(float4 &d, const uint32_t a[4],
                                         uint32_t b0, uint32_t b1) {
    asm volatile(
        "mma.sync.aligned.m16n8k16.row.col.f32.bf16.bf16.f32 "
        "{%0,%1,%2,%3}, {%4,%5,%6,%7}, {%8,%9}, {%0,%1,%2,%3};"
        : "+f"(d.x), "+f"(d.y), "+f"(d.z), "+f"(d.w)
        : "r"(a[0]), "r"(a[1]), "r"(a[2]), "r"(a[3]), "r"(b0), "r"(b1));
}

// ---------------------------------------------------------------------------
// Kernel 0: zero output + reset approx maxima
// ---------------------------------------------------------------------------
__global__ void init_kernel(float4 *out) {
    int i = blockIdx.x * blockDim.x + threadIdx.x;
    if (i < (BATCH * NN * NN) / 4) out[i] = make_float4(0.f, 0.f, 0.f, 0.f);
    if (blockIdx.x == 0 && threadIdx.x < BATCH * NSAMP) g_bestu[threadIdx.x] = 0u;
}

// ---------------------------------------------------------------------------
// Kernel 1: per-node layer-1 partials (8 nodes per block)
// ---------------------------------------------------------------------------
__global__ void precompute_kernel(const float *__restrict__ nodes,
                                  const float *__restrict__ W1) {
    int f  = threadIdx.x;
    int nb = blockIdx.x * 8;
    __shared__ float sn[8][FEAT];
#pragma unroll
    for (int k = 0; k < 8; ++k) sn[k][f] = nodes[(nb + k) * FEAT + f];
    __syncthreads();
    float a[8], bb[8];
#pragma unroll
    for (int k = 0; k < 8; ++k) { a[k] = 0.f; bb[k] = 0.f; }
    for (int i = 0; i < FEAT; ++i) {
        float wt = W1[i * FEAT + f];
        float wb = W1[(i + FEAT) * FEAT + f];
#pragma unroll
        for (int k = 0; k < 8; ++k) {
            a[k]  += sn[k][i] * wt;
            bb[k] += sn[k][i] * wb;
        }
    }
#pragma unroll
    for (int k = 0; k < 8; ++k) {
        g_A[(nb + k) * FEAT + f]  = a[k];
        g_Bm[(nb + k) * FEAT + f] = bb[k];
    }
}

// ---------------------------------------------------------------------------
// Kernel 2: bf16 HMMA approx pass. 128 edges per block, 4 warps.
// ---------------------------------------------------------------------------
extern __shared__ uint32_t smem_w[];

__global__ void __launch_bounds__(128)
main_mma(const float *__restrict__ b1,  const float *__restrict__ g1,
         const float *__restrict__ be1, const float *__restrict__ W2,
         const float *__restrict__ b2,  const float *__restrict__ g2,
         const float *__restrict__ be2, const float *__restrict__ W3,
         const float *__restrict__ b3) {
    const int tid = threadIdx.x, lane = tid & 31, warp = tid >> 5;
    const int gr = lane >> 2, tg = lane & 3;
    const int b = blockIdx.y;
    const int ebase = blockIdx.x * TILE_M;

    uint32_t *Xw = smem_w;                       // bf16 X tile [128][XS words]
    uint32_t *Ww = smem_w + 128 * XS;            // bf16 W2^T   [128][XS words]
    __shared__ float2   sPar[FEAT];              // (b2[c], g2[c]*W3[c])
    __shared__ float    sSP, sSQ;
    __shared__ unsigned sBest[NSAMP];

    // stage W2^T as bf16: Ww row n holds W2[:, n] over k
    {
        __nv_bfloat16 *W16 = (__nv_bfloat16 *)Ww;
        for (int idx = tid; idx < FEAT * FEAT; idx += 128) {
            int k = idx >> 7, n = idx & 127;
            W16[n * (2 * XS) + k] = __float2bfloat16(W2[idx]);
        }
    }
    // params
    sPar[tid] = make_float2(__ldg(b2 + tid), __ldg(g2 + tid) * __ldg(W3 + tid));
    if (tid < NSAMP) sBest[tid] = 0u;
    if (warp == 0) {
        float p = 0.f, q = 0.f;
#pragma unroll
        for (int c = lane; c < FEAT; c += 32) {
            float w3 = __ldg(W3 + c);
            p += __ldg(g2 + c) * w3;
            q += __ldg(be2 + c) * w3;
        }
        p = warp_sum(p);
        q = warp_sum(q);
        if (lane == 0) { sSP = p; sSQ = q; }
    }

    // Phase A: layer-1 + LN -> bf16 X rows (warp handles 32 edges)
    float c_b1[4], c_g1[4], c_be1[4];
#pragma unroll
    for (int k = 0; k < 4; ++k) {
        int f = lane * 4 + k;
        c_b1[k] = __ldg(b1 + f); c_g1[k] = __ldg(g1 + f); c_be1[k] = __ldg(be1 + f);
    }
    const float *Ab = g_A  + b * NN * FEAT;
    const float *Bb = g_Bm + b * NN * FEAT;
    const int m0 = warp * 32;
#pragma unroll 4
    for (int t = 0; t < 32; ++t) {
        int m = m0 + t;
        int r, c;
        decode_edge(ebase + m, r, c);
        float4 av = *(const float4 *)(Ab + r * FEAT + lane * 4);
        float4 bv = *(const float4 *)(Bb + c * FEAT + lane * 4);
        float h0 = fmaxf(av.x + bv.x + c_b1[0], 0.f);
        float h1 = fmaxf(av.y + bv.y + c_b1[1], 0.f);
        float h2 = fmaxf(av.z + bv.z + c_b1[2], 0.f);
        float h3 = fmaxf(av.w + bv.w + c_b1[3], 0.f);
        float mu = warp_sum(h0 + h1 + h2 + h3) * (1.f / 128.f);
        float d0 = h0 - mu, d1 = h1 - mu, d2 = h2 - mu, d3 = h3 - mu;
        float var = warp_sum(d0 * d0 + d1 * d1 + d2 * d2 + d3 * d3) * (1.f / 128.f);
        float inv = rsqrtf(var + 1e-5f);
        float x0 = d0 * inv * c_g1[0] + c_be1[0];
        float x1 = d1 * inv * c_g1[1] + c_be1[1];
        float x2 = d2 * inv * c_g1[2] + c_be1[2];
        float x3 = d3 * inv * c_g1[3] + c_be1[3];
        __nv_bfloat162 p0 = __floats2bfloat162_rn(x0, x1);
        __nv_bfloat162 p1 = __floats2bfloat162_rn(x2, x3);
        uint2 pk;
        pk.x = *(uint32_t *)&p0;
        pk.y = *(uint32_t *)&p1;
        *(uint2 *)(Xw + m * XS + lane * 2) = pk;
    }
    __syncthreads();

    // MMA: D[128,128] = X @ W2 ; warp owns 2 m16-tiles, 16 n8-tiles, 8 k16-steps
    float4 d[2][16];
#pragma unroll
    for (int mt = 0; mt < 2; ++mt)
#pragma unroll
        for (int nt = 0; nt < 16; ++nt) d[mt][nt] = make_float4(0.f, 0.f, 0.f, 0.f);

    for (int kt = 0; kt < 8; ++kt) {
        const int kw = kt * 8 + tg;
        uint32_t a[2][4];
#pragma unroll
        for (int mt = 0; mt < 2; ++mt) {
            int rowb = m0 + mt * 16 + gr;
            a[mt][0] = Xw[rowb * XS + kw];
            a[mt][1] = Xw[(rowb + 8) * XS + kw];
            a[mt][2] = Xw[rowb * XS + kw + 4];
            a[mt][3] = Xw[(rowb + 8) * XS + kw + 4];
        }
#pragma unroll
        for (int nt = 0; nt < 16; ++nt) {
            uint32_t b0 = Ww[(nt * 8 + gr) * XS + kw];
            uint32_t b1v = Ww[(nt * 8 + gr) * XS + kw + 4];
            mma16816(d[0][nt], a[0], b0, b1v);
            mma16816(d[1][nt], a[1], b0, b1v);
        }
    }

    // Epilogue in fragments: single pass -> S1, S2, SP per row-slot
    const float b3v = __ldg(b3);
    unsigned bestA = 0u, bestB = 0u;
#pragma unroll
    for (int rs = 0; rs < 4; ++rs) {
        const int mt = rs >> 1, hi = rs & 1;
        float S1 = 0.f, S2 = 0.f, SP = 0.f;
#pragma unroll
        for (int nt = 0; nt < 16; ++nt) {
            float4 par = *(const float4 *)&sPar[nt * 8 + tg * 2];
            float v0 = hi ? d[mt][nt].z : d[mt][nt].x;
            float v1 = hi ? d[mt][nt].w : d[mt][nt].y;
            float h0 = fmaxf(v0 + par.x, 0.f);
            float h1 = fmaxf(v1 + par.z, 0.f);
            S1 += h0 + h1;
            S2 += h0 * h0 + h1 * h1;
            SP += h0 * par.y + h1 * par.w;
        }
        S1 += __shfl_xor_sync(0xffffffffu, S1, 1);
        S1 += __shfl_xor_sync(0xffffffffu, S1, 2);
        S2 += __shfl_xor_sync(0xffffffffu, S2, 1);
        S2 += __shfl_xor_sync(0xffffffffu, S2, 2);
        SP += __shfl_xor_sync(0xffffffffu, SP, 1);
        SP += __shfl_xor_sync(0xffffffffu, SP, 2);
        float mu  = S1 * (1.f / 128.f);
        float var = fmaxf(S2 * (1.f / 128.f) - mu * mu, 0.f);
        float inv = rsqrtf(var + 1e-5f);
        float logit = inv * SP - mu * inv * sSP + sSQ + b3v;

        int e = ebase + m0 + mt * 16 + hi * 8 + gr;
        unsigned j = (unsigned)((b * NSAMP + tg) * E_CNT + e);
        float sc = logit + gumbel_from_bits(threefry_bits(j));
        g_scores[j] = sc;
        bestA = max(bestA, flipf(sc));
        if (tg == 0) {
            unsigned j4 = (unsigned)((b * NSAMP + 4) * E_CNT + e);
            float sc4 = logit + gumbel_from_bits(threefry_bits(j4));
            g_scores[j4] = sc4;
            bestB = max(bestB, flipf(sc4));
        }
    }
    bestA = max(bestA, __shfl_xor_sync(0xffffffffu, bestA, 4));
    bestA = max(bestA, __shfl_xor_sync(0xffffffffu, bestA, 8));
    bestA = max(bestA, __shfl_xor_sync(0xffffffffu, bestA, 16));
    bestB = max(bestB, __shfl_xor_sync(0xffffffffu, bestB, 4));
    bestB = max(bestB, __shfl_xor_sync(0xffffffffu, bestB, 8));
    bestB = max(bestB, __shfl_xor_sync(0xffffffffu, bestB, 16));
    if (lane < 4) atomicMax(&sBest[lane], bestA);
    if (lane == 0) atomicMax(&sBest[4], bestB);
    __syncthreads();
    if (tid < NSAMP) atomicMax(&g_bestu[b * NSAMP + tid], sBest[tid]);
}

// ---------------------------------------------------------------------------
// Exact fp32 score for one edge, warp-collective (R2/R3-validated op order)
// ---------------------------------------------------------------------------
__device__ float exact_score(int e, int b, int s,
                             const float *W2, const float *b1, const float *g1,
                             const float *be1, const float *b2, const float *g2,
                             const float *be2, const float *W3, const float *b3,
                             int lane) {
    int r, c;
    decode_edge(e, r, c);
    const float *Ab = g_A  + b * NN * FEAT;
    const float *Bb = g_Bm + b * NN * FEAT;
    float4 av = *(const float4 *)(Ab + r * FEAT + lane * 4);
    float4 bv = *(const float4 *)(Bb + c * FEAT + lane * 4);
    int f = lane * 4;
    float h0 = fmaxf(av.x + bv.x + __ldg(b1 + f + 0), 0.f);
    float h1 = fmaxf(av.y + bv.y + __ldg(b1 + f + 1), 0.f);
    float h2 = fmaxf(av.z + bv.z + __ldg(b1 + f + 2), 0.f);
    float h3 = fmaxf(av.w + bv.w + __ldg(b1 + f + 3), 0.f);
    float mu = warp_sum(h0 + h1 + h2 + h3) * (1.f / 128.f);
    float d0 = h0 - mu, d1 = h1 - mu, d2 = h2 - mu, d3 = h3 - mu;
    float var = warp_sum(d0 * d0 + d1 * d1 + d2 * d2 + d3 * d3) * (1.f / 128.f);
    float inv = rsqrtf(var + 1e-5f);
    float x0 = d0 * inv * __ldg(g1 + f + 0) + __ldg(be1 + f + 0);
    float x1 = d1 * inv * __ldg(g1 + f + 1) + __ldg(be1 + f + 1);
    float x2 = d2 * inv * __ldg(g1 + f + 2) + __ldg(be1 + f + 2);
    float x3 = d3 * inv * __ldg(g1 + f + 3) + __ldg(be1 + f + 3);

    float a0 = 0.f, a1 = 0.f, a2 = 0.f, a3 = 0.f;
    for (int src = 0; src < 32; ++src) {
        float v0 = __shfl_sync(0xffffffffu, x0, src);
        float v1 = __shfl_sync(0xffffffffu, x1, src);
        float v2 = __shfl_sync(0xffffffffu, x2, src);
        float v3 = __shfl_sync(0xffffffffu, x3, src);
        float4 w;
        w = *(const float4 *)(W2 + (src * 4 + 0) * FEAT + f);
        a0 += v0 * w.x; a1 += v0 * w.y; a2 += v0 * w.z; a3 += v0 * w.w;
        w = *(const float4 *)(W2 + (src * 4 + 1) * FEAT + f);
        a0 += v1 * w.x; a1 += v1 * w.y; a2 += v1 * w.z; a3 += v1 * w.w;
        w = *(const float4 *)(W2 + (src * 4 + 2) * FEAT + f);
        a0 += v2 * w.x; a1 += v2 * w.y; a2 += v2 * w.z; a3 += v2 * w.w;
        w = *(const float4 *)(W2 + (src * 4 + 3) * FEAT + f);
        a0 += v3 * w.x; a1 += v3 * w.y; a2 += v3 * w.z; a3 += v3 * w.w;
    }
    h0 = fmaxf(a0 + __ldg(b2 + f + 0), 0.f);
    h1 = fmaxf(a1 + __ldg(b2 + f + 1), 0.f);
    h2 = fmaxf(a2 + __ldg(b2 + f + 2), 0.f);
    h3 = fmaxf(a3 + __ldg(b2 + f + 3), 0.f);
    mu = warp_sum(h0 + h1 + h2 + h3) * (1.f / 128.f);
    d0 = h0 - mu; d1 = h1 - mu; d2 = h2 - mu; d3 = h3 - mu;
    var = warp_sum(d0 * d0 + d1 * d1 + d2 * d2 + d3 * d3) * (1.f / 128.f);
    inv = rsqrtf(var + 1e-5f);
    float y0 = d0 * inv * __ldg(g2 + f + 0) + __ldg(be2 + f + 0);
    float y1 = d1 * inv * __ldg(g2 + f + 1) + __ldg(be2 + f + 1);
    float y2 = d2 * inv * __ldg(g2 + f + 2) + __ldg(be2 + f + 2);
    float y3 = d3 * inv * __ldg(g2 + f + 3) + __ldg(be2 + f + 3);
    float logit = warp_sum(y0 * __ldg(W3 + f + 0) + y1 * __ldg(W3 + f + 1) +
                           y2 * __ldg(W3 + f + 2) + y3 * __ldg(W3 + f + 3)) + __ldg(b3);
    unsigned j = (unsigned)((b * NSAMP + s) * E_CNT + e);
    return logit + gumbel_from_bits(threefry_bits(j));
}

// ---------------------------------------------------------------------------
// Kernel 3: per-(b,s) candidate collection + exact refinement + argmax
// ---------------------------------------------------------------------------
__global__ void __launch_bounds__(256)
refine_kernel(const float *__restrict__ W2, const float *__restrict__ b1,
              const float *__restrict__ g1, const float *__restrict__ be1,
              const float *__restrict__ b2, const float *__restrict__ g2,
              const float *__restrict__ be2, const float *__restrict__ W3,
              const float *__restrict__ b3) {
    const int bs = blockIdx.x;
    const int b = bs / NSAMP, s = bs % NSAMP;
    __shared__ int   s_cnt;
    __shared__ int   s_cand[MAXC];
    __shared__ float s_score[MAXC];
    if (threadIdx.x == 0) s_cnt = 0;
    __syncthreads();

    const float bestA = unflipf(g_bestu[bs]);
    const float thr = bestA - DELTA;
    const float *sc = g_scores + bs * E_CNT;
    for (int e = threadIdx.x; e < E_CNT; e += blockDim.x) {
        if (sc[e] >= thr) {
            int i = atomicAdd(&s_cnt, 1);
            if (i < MAXC) s_cand[i] = e;
        }
    }
    __syncthreads();
    int n = min(s_cnt, MAXC);

    const int warp = threadIdx.x >> 5, lane = threadIdx.x & 31;
    for (int i = warp; i < n; i += 8) {
        float v = exact_score(s_cand[i], b, s, W2, b1, g1, be1, b2, g2, be2, W3, b3, lane);
        if (lane == 0) s_score[i] = v;
    }
    __syncthreads();
    if (threadIdx.x == 0) {
        float best = -__int_as_float(0x7f800000);
        int beste = 0x7FFFFFFF;
        for (int i = 0; i < n; ++i) {
            if (s_score[i] > best || (s_score[i] == best && s_cand[i] < beste)) {
                best = s_score[i];
                beste = s_cand[i];
            }
        }
        g_winner[bs] = beste;
    }
}

// ---------------------------------------------------------------------------
// Kernel 4: scatter winners
// ---------------------------------------------------------------------------
__global__ void finalize_kernel(float *out) {
    int t = threadIdx.x;
    if (t >= BATCH * NSAMP) return;
    int e = g_winner[t];
    int b = t / NSAMP;
    int r, c;
    decode_edge(e, r, c);
    out[b * NN * NN + r * NN + c] = 1.0f;
}

// ---------------------------------------------------------------------------
extern "C" void kernel_launch(void *const *d_in, const int *in_sizes, int n_in,
                              void *d_out, int out_size) {
    const float *nodes = (const float *)d_in[0];
    const float *W1    = (const float *)d_in[1];
    const float *b1    = (const float *)d_in[2];
    const float *g1    = (const float *)d_in[3];
    const float *be1   = (const float *)d_in[4];
    const float *W2    = (const float *)d_in[5];
    const float *b2    = (const float *)d_in[6];
    const float *g2    = (const float *)d_in[7];
    const float *be2   = (const float *)d_in[8];
    const float *W3    = (const float *)d_in[9];
    const float *b3    = (const float *)d_in[10];

    cudaFuncSetAttribute(main_mma, cudaFuncAttributeMaxDynamicSharedMemorySize, SMEM_MAIN);

    init_kernel<<<1024, 256>>>((float4 *)d_out);
    precompute_kernel<<<BATCH * NN / 8, FEAT>>>(nodes, W1);
    main_mma<<<dim3(NTILE, BATCH), 128, SMEM_MAIN>>>(
        b1, g1, be1, W2, b2, g2, be2, W3, b3);
    refine_kernel<<<BATCH * NSAMP, 256>>>(W2, b1, g1, be1, b2, g2, be2, W3, b3);
    finalize_kernel<<<1, 32>>>((float *)d_out);
}

// round 10
// speedup vs baseline: 1.0014x; 1.0008x over previous
#include <cuda_runtime.h>
#include <cuda_bf16.h>
#include <math.h>
#include <stdint.h>

#define FEAT   128
#define NN     512
#define BATCH  4
#define NSAMP  5
#define E_CNT  97920
#define BASE0  32896
#define TILE_M 128
#define NTILE  (E_CNT / TILE_M)     // 765
#define DELTA  0.125f
#define MAXC   128
#define XS     68                   // word stride of bf16 tiles (conflict-free)
#define SMEM_X_BYTES (128 * XS * 4) // 34816
#define SMEM_MAIN (2 * SMEM_X_BYTES)

// ---------------------------------------------------------------------------
// Scratch (static device globals: no allocation allowed)
// ---------------------------------------------------------------------------
__device__ float    g_A[BATCH * NN * FEAT];
__device__ float    g_Bm[BATCH * NN * FEAT];
__device__ float    g_scores[BATCH * NSAMP * E_CNT];   // 7.8 MB
__device__ unsigned g_bestu[BATCH * NSAMP];            // flipped-float approx max
__device__ int      g_winner[BATCH * NSAMP];

// ---------------------------------------------------------------------------
// helpers
// ---------------------------------------------------------------------------
__device__ __forceinline__ unsigned flipf(float f) {
    unsigned u = __float_as_uint(f);
    return (u & 0x80000000u) ? ~u : (u | 0x80000000u);
}
__device__ __forceinline__ float unflipf(unsigned u) {
    return __uint_as_float((u & 0x80000000u) ? (u & 0x7FFFFFFFu) : ~u);
}
__device__ __forceinline__ unsigned rotl32(unsigned v, int s) {
    return (v << s) | (v >> (32 - s));
}
// JAX Threefry-2x32, key (0,42), partitionable: bits[j] = v0^v1 of tf((0,42),(0,j))
__device__ __forceinline__ unsigned threefry_bits(unsigned j) {
    const unsigned ks0 = 0u, ks1 = 42u, ks2 = 0x1BD11BDAu ^ 42u;
    unsigned x0 = ks0, x1 = j + ks1;
#define RND(r) { x0 += x1; x1 = rotl32(x1, (r)); x1 ^= x0; }
    RND(13) RND(15) RND(26) RND(6)
    x0 += ks1; x1 += ks2 + 1u;
    RND(17) RND(29) RND(16) RND(24)
    x0 += ks2; x1 += ks0 + 2u;
    RND(13) RND(15) RND(26) RND(6)
    x0 += ks0; x1 += ks1 + 3u;
    RND(17) RND(29) RND(16) RND(24)
    x0 += ks1; x1 += ks2 + 4u;
    RND(13) RND(15) RND(26) RND(6)
    x0 += ks2; x1 += ks0 + 5u;
#undef RND
    return x0 ^ x1;
}
__device__ __forceinline__ float gumbel_from_bits(unsigned bits) {
    unsigned m = bits >> 9;
    float u;
    if (m == 0u) u = 1.17549435e-38f;
    else         u = __uint_as_float(0x3F800000u | m) - 1.0f;
    return -logf(-logf(u));
}
__device__ __forceinline__ void decode_edge(int e, int &r, int &c) {
    int t = e + BASE0;
    int rr = (int)((1.0f + sqrtf(8.0f * (float)t + 1.0f)) * 0.5f);
    while (rr * (rr - 1) / 2 > t) --rr;
    while ((rr + 1) * rr / 2 <= t) ++rr;
    r = rr;
    c = t - rr * (rr - 1) / 2;
}
__device__ __forceinline__ float warp_sum(float v) {
    v += __shfl_xor_sync(0xffffffffu, v, 16);
    v += __shfl_xor_sync(0xffffffffu, v, 8);
    v += __shfl_xor_sync(0xffffffffu, v, 4);
    v += __shfl_xor_sync(0xffffffffu, v, 2);
    v += __shfl_xor_sync(0xffffffffu, v, 1);
    return v;
}
// bf16 HMMA m16n8k16, row.col, fp32 accum
__device__ __forceinline__ void mma16816(float4 &d, const uint32_t a[4],
                                         uint32_t b0, uint32_t b1) {
    asm volatile(
        "mma.sync.aligned.m16n8k16.row.col.f32.bf16.bf16.f32 "
        "{%0,%1,%2,%3}, {%4,%5,%6,%7}, {%8,%9}, {%0,%1,%2,%3};"
        : "+f"(d.x), "+f"(d.y), "+f"(d.z), "+f"(d.w)
        : "r"(a[0]), "r"(a[1]), "r"(a[2]), "r"(a[3]), "r"(b0), "r"(b1));
}

// ---------------------------------------------------------------------------
// Kernel 0: zero output + reset approx maxima
// ---------------------------------------------------------------------------
__global__ void init_kernel(float4 *out) {
    int i = blockIdx.x * blockDim.x + threadIdx.x;
    if (i < (BATCH * NN * NN) / 4) out[i] = make_float4(0.f, 0.f, 0.f, 0.f);
    if (blockIdx.x == 0 && threadIdx.x < BATCH * NSAMP) g_bestu[threadIdx.x] = 0u;
}

// ---------------------------------------------------------------------------
// Kernel 1: per-node layer-1 partials (8 nodes per block)
// ---------------------------------------------------------------------------
__global__ void precompute_kernel(const float *__restrict__ nodes,
                                  const float *__restrict__ W1) {
    int f  = threadIdx.x;
    int nb = blockIdx.x * 8;
    __shared__ float sn[8][FEAT];
#pragma unroll
    for (int k = 0; k < 8; ++k) sn[k][f] = nodes[(nb + k) * FEAT + f];
    __syncthreads();
    float a[8], bb[8];
#pragma unroll
    for (int k = 0; k < 8; ++k) { a[k] = 0.f; bb[k] = 0.f; }
    for (int i = 0; i < FEAT; ++i) {
        float wt = W1[i * FEAT + f];
        float wb = W1[(i + FEAT) * FEAT + f];
#pragma unroll
        for (int k = 0; k < 8; ++k) {
            a[k]  += sn[k][i] * wt;
            bb[k] += sn[k][i] * wb;
        }
    }
#pragma unroll
    for (int k = 0; k < 8; ++k) {
        g_A[(nb + k) * FEAT + f]  = a[k];
        g_Bm[(nb + k) * FEAT + f] = bb[k];
    }
}

// ---------------------------------------------------------------------------
// Kernel 2: bf16 HMMA approx pass. 128 edges per block, 4 warps.
// ---------------------------------------------------------------------------
extern __shared__ uint32_t smem_w[];

__global__ void __launch_bounds__(128)
main_mma(const float *__restrict__ b1,  const float *__restrict__ g1,
         const float *__restrict__ be1, const float *__restrict__ W2,
         const float *__restrict__ b2,  const float *__restrict__ g2,
         const float *__restrict__ be2, const float *__restrict__ W3,
         const float *__restrict__ b3) {
    const int tid = threadIdx.x, lane = tid & 31, warp = tid >> 5;
    const int gr = lane >> 2, tg = lane & 3;
    const int b = blockIdx.y;
    const int ebase = blockIdx.x * TILE_M;

    uint32_t *Xw = smem_w;                       // bf16 X tile [128][XS words]
    uint32_t *Ww = smem_w + 128 * XS;            // bf16 W2^T   [128][XS words]
    __shared__ float2   sPar[FEAT];              // (b2[c], g2[c]*W3[c])
    __shared__ float    sSP, sSQ;
    __shared__ unsigned sBest[NSAMP];

    // stage W2^T as bf16: Ww row n holds W2[:, n] over k
    {
        __nv_bfloat16 *W16 = (__nv_bfloat16 *)Ww;
        for (int idx = tid; idx < FEAT * FEAT; idx += 128) {
            int k = idx >> 7, n = idx & 127;
            W16[n * (2 * XS) + k] = __float2bfloat16(W2[idx]);
        }
    }
    // params
    sPar[tid] = make_float2(__ldg(b2 + tid), __ldg(g2 + tid) * __ldg(W3 + tid));
    if (tid < NSAMP) sBest[tid] = 0u;
    if (warp == 0) {
        float p = 0.f, q = 0.f;
#pragma unroll
        for (int c = lane; c < FEAT; c += 32) {
            float w3 = __ldg(W3 + c);
            p += __ldg(g2 + c) * w3;
            q += __ldg(be2 + c) * w3;
        }
        p = warp_sum(p);
        q = warp_sum(q);
        if (lane == 0) { sSP = p; sSQ = q; }
    }

    // Phase A: layer-1 + LN -> bf16 X rows (warp handles 32 edges)
    float c_b1[4], c_g1[4], c_be1[4];
#pragma unroll
    for (int k = 0; k < 4; ++k) {
        int f = lane * 4 + k;
        c_b1[k] = __ldg(b1 + f); c_g1[k] = __ldg(g1 + f); c_be1[k] = __ldg(be1 + f);
    }
    const float *Ab = g_A  + b * NN * FEAT;
    const float *Bb = g_Bm + b * NN * FEAT;
    const int m0 = warp * 32;
#pragma unroll 4
    for (int t = 0; t < 32; ++t) {
        int m = m0 + t;
        int r, c;
        decode_edge(ebase + m, r, c);
        float4 av = *(const float4 *)(Ab + r * FEAT + lane * 4);
        float4 bv = *(const float4 *)(Bb + c * FEAT + lane * 4);
        float h0 = fmaxf(av.x + bv.x + c_b1[0], 0.f);
        float h1 = fmaxf(av.y + bv.y + c_b1[1], 0.f);
        float h2 = fmaxf(av.z + bv.z + c_b1[2], 0.f);
        float h3 = fmaxf(av.w + bv.w + c_b1[3], 0.f);
        float mu = warp_sum(h0 + h1 + h2 + h3) * (1.f / 128.f);
        float d0 = h0 - mu, d1 = h1 - mu, d2 = h2 - mu, d3 = h3 - mu;
        float var = warp_sum(d0 * d0 + d1 * d1 + d2 * d2 + d3 * d3) * (1.f / 128.f);
        float inv = rsqrtf(var + 1e-5f);
        float x0 = d0 * inv * c_g1[0] + c_be1[0];
        float x1 = d1 * inv * c_g1[1] + c_be1[1];
        float x2 = d2 * inv * c_g1[2] + c_be1[2];
        float x3 = d3 * inv * c_g1[3] + c_be1[3];
        __nv_bfloat162 p0 = __floats2bfloat162_rn(x0, x1);
        __nv_bfloat162 p1 = __floats2bfloat162_rn(x2, x3);
        uint2 pk;
        pk.x = *(uint32_t *)&p0;
        pk.y = *(uint32_t *)&p1;
        *(uint2 *)(Xw + m * XS + lane * 2) = pk;
    }
    __syncthreads();

    // MMA: D[128,128] = X @ W2 ; warp owns 2 m16-tiles, 16 n8-tiles, 8 k16-steps
    float4 d[2][16];
#pragma unroll
    for (int mt = 0; mt < 2; ++mt)
#pragma unroll
        for (int nt = 0; nt < 16; ++nt) d[mt][nt] = make_float4(0.f, 0.f, 0.f, 0.f);

    for (int kt = 0; kt < 8; ++kt) {
        const int kw = kt * 8 + tg;
        uint32_t a[2][4];
#pragma unroll
        for (int mt = 0; mt < 2; ++mt) {
            int rowb = m0 + mt * 16 + gr;
            a[mt][0] = Xw[rowb * XS + kw];
            a[mt][1] = Xw[(rowb + 8) * XS + kw];
            a[mt][2] = Xw[rowb * XS + kw + 4];
            a[mt][3] = Xw[(rowb + 8) * XS + kw + 4];
        }
#pragma unroll
        for (int nt = 0; nt < 16; ++nt) {
            uint32_t b0 = Ww[(nt * 8 + gr) * XS + kw];
            uint32_t b1v = Ww[(nt * 8 + gr) * XS + kw + 4];
            mma16816(d[0][nt], a[0], b0, b1v);
            mma16816(d[1][nt], a[1], b0, b1v);
        }
    }

    // Epilogue in fragments: single pass -> S1, S2, SP per row-slot
    const float b3v = __ldg(b3);
    unsigned bestA = 0u, bestB = 0u;
#pragma unroll
    for (int rs = 0; rs < 4; ++rs) {
        const int mt = rs >> 1, hi = rs & 1;
        float S1 = 0.f, S2 = 0.f, SP = 0.f;
#pragma unroll
        for (int nt = 0; nt < 16; ++nt) {
            float4 par = *(const float4 *)&sPar[nt * 8 + tg * 2];
            float v0 = hi ? d[mt][nt].z : d[mt][nt].x;
            float v1 = hi ? d[mt][nt].w : d[mt][nt].y;
            float h0 = fmaxf(v0 + par.x, 0.f);
            float h1 = fmaxf(v1 + par.z, 0.f);
            S1 += h0 + h1;
            S2 += h0 * h0 + h1 * h1;
            SP += h0 * par.y + h1 * par.w;
        }
        S1 += __shfl_xor_sync(0xffffffffu, S1, 1);
        S1 += __shfl_xor_sync(0xffffffffu, S1, 2);
        S2 += __shfl_xor_sync(0xffffffffu, S2, 1);
        S2 += __shfl_xor_sync(0xffffffffu, S2, 2);
        SP += __shfl_xor_sync(0xffffffffu, SP, 1);
        SP += __shfl_xor_sync(0xffffffffu, SP, 2);
        float mu  = S1 * (1.f / 128.f);
        float var = fmaxf(S2 * (1.f / 128.f) - mu * mu, 0.f);
        float inv = rsqrtf(var + 1e-5f);
        float logit = inv * SP - mu * inv * sSP + sSQ + b3v;

        int e = ebase + m0 + mt * 16 + hi * 8 + gr;
        unsigned j = (unsigned)((b * NSAMP + tg) * E_CNT + e);
        float sc = logit + gumbel_from_bits(threefry_bits(j));
        g_scores[j] = sc;
        bestA = max(bestA, flipf(sc));
        if (tg == 0) {
            unsigned j4 = (unsigned)((b * NSAMP + 4) * E_CNT + e);
            float sc4 = logit + gumbel_from_bits(threefry_bits(j4));
            g_scores[j4] = sc4;
            bestB = max(bestB, flipf(sc4));
        }
    }
    bestA = max(bestA, __shfl_xor_sync(0xffffffffu, bestA, 4));
    bestA = max(bestA, __shfl_xor_sync(0xffffffffu, bestA, 8));
    bestA = max(bestA, __shfl_xor_sync(0xffffffffu, bestA, 16));
    bestB = max(bestB, __shfl_xor_sync(0xffffffffu, bestB, 4));
    bestB = max(bestB, __shfl_xor_sync(0xffffffffu, bestB, 8));
    bestB = max(bestB, __shfl_xor_sync(0xffffffffu, bestB, 16));
    if (lane < 4) atomicMax(&sBest[lane], bestA);
    if (lane == 0) atomicMax(&sBest[4], bestB);
    __syncthreads();
    if (tid < NSAMP) atomicMax(&g_bestu[b * NSAMP + tid], sBest[tid]);
}

// ---------------------------------------------------------------------------
// Exact fp32 score for one edge, warp-collective (R2/R3-validated op order)
// ---------------------------------------------------------------------------
__device__ float exact_score(int e, int b, int s,
                             const float *W2, const float *b1, const float *g1,
                             const float *be1, const float *b2, const float *g2,
                             const float *be2, const float *W3, const float *b3,
                             int lane) {
    int r, c;
    decode_edge(e, r, c);
    const float *Ab = g_A  + b * NN * FEAT;
    const float *Bb = g_Bm + b * NN * FEAT;
    float4 av = *(const float4 *)(Ab + r * FEAT + lane * 4);
    float4 bv = *(const float4 *)(Bb + c * FEAT + lane * 4);
    int f = lane * 4;
    float h0 = fmaxf(av.x + bv.x + __ldg(b1 + f + 0), 0.f);
    float h1 = fmaxf(av.y + bv.y + __ldg(b1 + f + 1), 0.f);
    float h2 = fmaxf(av.z + bv.z + __ldg(b1 + f + 2), 0.f);
    float h3 = fmaxf(av.w + bv.w + __ldg(b1 + f + 3), 0.f);
    float mu = warp_sum(h0 + h1 + h2 + h3) * (1.f / 128.f);
    float d0 = h0 - mu, d1 = h1 - mu, d2 = h2 - mu, d3 = h3 - mu;
    float var = warp_sum(d0 * d0 + d1 * d1 + d2 * d2 + d3 * d3) * (1.f / 128.f);
    float inv = rsqrtf(var + 1e-5f);
    float x0 = d0 * inv * __ldg(g1 + f + 0) + __ldg(be1 + f + 0);
    float x1 = d1 * inv * __ldg(g1 + f + 1) + __ldg(be1 + f + 1);
    float x2 = d2 * inv * __ldg(g1 + f + 2) + __ldg(be1 + f + 2);
    float x3 = d3 * inv * __ldg(g1 + f + 3) + __ldg(be1 + f + 3);

    float a0 = 0.f, a1 = 0.f, a2 = 0.f, a3 = 0.f;
    for (int src = 0; src < 32; ++src) {
        float v0 = __shfl_sync(0xffffffffu, x0, src);
        float v1 = __shfl_sync(0xffffffffu, x1, src);
        float v2 = __shfl_sync(0xffffffffu, x2, src);
        float v3 = __shfl_sync(0xffffffffu, x3, src);
        float4 w;
        w = *(const float4 *)(W2 + (src * 4 + 0) * FEAT + f);
        a0 += v0 * w.x; a1 += v0 * w.y; a2 += v0 * w.z; a3 += v0 * w.w;
        w = *(const float4 *)(W2 + (src * 4 + 1) * FEAT + f);
        a0 += v1 * w.x; a1 += v1 * w.y; a2 += v1 * w.z; a3 += v1 * w.w;
        w = *(const float4 *)(W2 + (src * 4 + 2) * FEAT + f);
        a0 += v2 * w.x; a1 += v2 * w.y; a2 += v2 * w.z; a3 += v2 * w.w;
        w = *(const float4 *)(W2 + (src * 4 + 3) * FEAT + f);
        a0 += v3 * w.x; a1 += v3 * w.y; a2 += v3 * w.z; a3 += v3 * w.w;
    }
    h0 = fmaxf(a0 + __ldg(b2 + f + 0), 0.f);
    h1 = fmaxf(a1 + __ldg(b2 + f + 1), 0.f);
    h2 = fmaxf(a2 + __ldg(b2 + f + 2), 0.f);
    h3 = fmaxf(a3 + __ldg(b2 + f + 3), 0.f);
    mu = warp_sum(h0 + h1 + h2 + h3) * (1.f / 128.f);
    d0 = h0 - mu; d1 = h1 - mu; d2 = h2 - mu; d3 = h3 - mu;
    var = warp_sum(d0 * d0 + d1 * d1 + d2 * d2 + d3 * d3) * (1.f / 128.f);
    inv = rsqrtf(var + 1e-5f);
    float y0 = d0 * inv * __ldg(g2 + f + 0) + __ldg(be2 + f + 0);
    float y1 = d1 * inv * __ldg(g2 + f + 1) + __ldg(be2 + f + 1);
    float y2 = d2 * inv * __ldg(g2 + f + 2) + __ldg(be2 + f + 2);
    float y3 = d3 * inv * __ldg(g2 + f + 3) + __ldg(be2 + f + 3);
    float logit = warp_sum(y0 * __ldg(W3 + f + 0) + y1 * __ldg(W3 + f + 1) +
                           y2 * __ldg(W3 + f + 2) + y3 * __ldg(W3 + f + 3)) + __ldg(b3);
    unsigned j = (unsigned)((b * NSAMP + s) * E_CNT + e);
    return logit + gumbel_from_bits(threefry_bits(j));
}

// ---------------------------------------------------------------------------
// Kernel 3: per-(b,s) candidate collection + exact refinement + argmax
// ---------------------------------------------------------------------------
__global__ void __launch_bounds__(256)
refine_kernel(const float *__restrict__ W2, const float *__restrict__ b1,
              const float *__restrict__ g1, const float *__restrict__ be1,
              const float *__restrict__ b2, const float *__restrict__ g2,
              const float *__restrict__ be2, const float *__restrict__ W3,
              const float *__restrict__ b3) {
    const int bs = blockIdx.x;
    const int b = bs / NSAMP, s = bs % NSAMP;
    __shared__ int   s_cnt;
    __shared__ int   s_cand[MAXC];
    __shared__ float s_score[MAXC];
    if (threadIdx.x == 0) s_cnt = 0;
    __syncthreads();

    const float bestA = unflipf(g_bestu[bs]);
    const float thr = bestA - DELTA;
    const float *sc = g_scores + bs * E_CNT;
    for (int e = threadIdx.x; e < E_CNT; e += blockDim.x) {
        if (sc[e] >= thr) {
            int i = atomicAdd(&s_cnt, 1);
            if (i < MAXC) s_cand[i] = e;
        }
    }
    __syncthreads();
    int n = min(s_cnt, MAXC);

    const int warp = threadIdx.x >> 5, lane = threadIdx.x & 31;
    for (int i = warp; i < n; i += 8) {
        float v = exact_score(s_cand[i], b, s, W2, b1, g1, be1, b2, g2, be2, W3, b3, lane);
        if (lane == 0) s_score[i] = v;
    }
    __syncthreads();
    if (threadIdx.x == 0) {
        float best = -__int_as_float(0x7f800000);
        int beste = 0x7FFFFFFF;
        for (int i = 0; i < n; ++i) {
            if (s_score[i] > best || (s_score[i] == best && s_cand[i] < beste)) {
                best = s_score[i];
                beste = s_cand[i];
            }
        }
        g_winner[bs] = beste;
    }
}

// ---------------------------------------------------------------------------
// Kernel 4: scatter winners
// ---------------------------------------------------------------------------
__global__ void finalize_kernel(float *out) {
    int t = threadIdx.x;
    if (t >= BATCH * NSAMP) return;
    int e = g_winner[t];
    int b = t / NSAMP;
    int r, c;
    decode_edge(e, r, c);
    out[b * NN * NN + r * NN + c] = 1.0f;
}

// ---------------------------------------------------------------------------
extern "C" void kernel_launch(void *const *d_in, const int *in_sizes, int n_in,
                              void *d_out, int out_size) {
    const float *nodes = (const float *)d_in[0];
    const float *W1    = (const float *)d_in[1];
    const float *b1    = (const float *)d_in[2];
    const float *g1    = (const float *)d_in[3];
    const float *be1   = (const float *)d_in[4];
    const float *W2    = (const float *)d_in[5];
    const float *b2    = (const float *)d_in[6];
    const float *g2    = (const float *)d_in[7];
    const float *be2   = (const float *)d_in[8];
    const float *W3    = (const float *)d_in[9];
    const float *b3    = (const float *)d_in[10];

    cudaFuncSetAttribute(main_mma, cudaFuncAttributeMaxDynamicSharedMemorySize, SMEM_MAIN);

    init_kernel<<<1024, 256>>>((float4 *)d_out);
    precompute_kernel<<<BATCH * NN / 8, FEAT>>>(nodes, W1);
    main_mma<<<dim3(NTILE, BATCH), 128, SMEM_MAIN>>>(
        b1, g1, be1, W2, b2, g2, be2, W3, b3);
    refine_kernel<<<BATCH * NSAMP, 256>>>(W2, b1, g1, be1, b2, g2, be2, W3, b3);
    finalize_kernel<<<1, 32>>>((float *)d_out);
}